// round 13
// baseline (speedup 1.0000x reference)
#include <cuda_runtime.h>
#include <cuda_fp16.h>
#include <cstdint>
#include <math.h>

#define BB 16
#define CC 512
#define LL 1024
#define GG 32
#define CPG 16
#define HEADS 8
#define CHH 64

// Scratch (no allocation allowed)
__device__ __half g_hT[BB * LL * CC];                 // h transposed [b][l][c], fp16
__device__ __half g_wh[3 * CC * CC];                  // conv weight fp16
__device__ __half g_qkT[BB * 2 * HEADS * LL * CHH];   // q,k transposed; q pre-scaled by 0.125*log2(e)
__device__ __half g_v[BB * CC * LL];                  // v natural [b][ch_global][l]

__device__ __forceinline__ void mma_f16(float d[4], const unsigned a[4], const unsigned b[2]) {
    asm volatile(
        "mma.sync.aligned.m16n8k16.row.col.f32.f16.f16.f32 "
        "{%0,%1,%2,%3}, {%4,%5,%6,%7}, {%8,%9}, {%0,%1,%2,%3};"
        : "+f"(d[0]), "+f"(d[1]), "+f"(d[2]), "+f"(d[3])
        : "r"(a[0]), "r"(a[1]), "r"(a[2]), "r"(a[3]),
          "r"(b[0]), "r"(b[1]));
}

__device__ __forceinline__ void ldsm4(unsigned r[4], unsigned saddr) {
    asm volatile("ldmatrix.sync.aligned.m8n8.x4.shared.b16 {%0,%1,%2,%3}, [%4];"
                 : "=r"(r[0]), "=r"(r[1]), "=r"(r[2]), "=r"(r[3]) : "r"(saddr));
}

__device__ __forceinline__ unsigned ex2_f16x2(unsigned v) {
    unsigned r;
    asm("ex2.approx.f16x2 %0, %1;" : "=r"(r) : "r"(v));
    return r;
}

__device__ __forceinline__ void cp16h(__half* dst_smem, const __half* src) {
    unsigned d = (unsigned)__cvta_generic_to_shared(dst_smem);
    asm volatile("cp.async.cg.shared.global [%0], [%1], 16;" :: "r"(d), "l"(src));
}
__device__ __forceinline__ void cp_commit() { asm volatile("cp.async.commit_group;"); }
__device__ __forceinline__ void cp_wait1() { asm volatile("cp.async.wait_group 1;"); }

// ---------------------------------------------------------------------------
// Kernel 0: convert conv weight to fp16.
// ---------------------------------------------------------------------------
__global__ void wconv_kernel(const float* __restrict__ W) {
    int i = blockIdx.x * 256 + threadIdx.x;
    float2 w = ((const float2*)W)[i];
    ((__half2*)g_wh)[i] = __floats2half2_rn(w.x, w.y);
}

// ---------------------------------------------------------------------------
// Kernel 1: GroupNorm(32) -> hT [b][l][c] fp16. One block per (b, g).
// ---------------------------------------------------------------------------
__global__ void gn_kernel(const float* __restrict__ x,
                          const float* __restrict__ gw,
                          const float* __restrict__ gb) {
    int bg = blockIdx.x;
    int b = bg >> 5, g = bg & 31;
    const float* xp = x + ((size_t)b * CC + (size_t)g * CPG) * LL;
    const float4* xp4 = (const float4*)xp;
    int t = threadIdx.x;

    float s = 0.f, ss = 0.f;
    for (int i = t; i < CPG * LL / 4; i += 256) {
        float4 v = xp4[i];
        s += v.x + v.y + v.z + v.w;
        ss += v.x * v.x + v.y * v.y + v.z * v.z + v.w * v.w;
    }
    __shared__ float r0[256], r1[256];
    r0[t] = s; r1[t] = ss;
    __syncthreads();
    for (int o = 128; o > 0; o >>= 1) {
        if (t < o) { r0[t] += r0[t + o]; r1[t] += r1[t + o]; }
        __syncthreads();
    }
    const float invN = 1.f / (CPG * LL);
    float mean = r0[0] * invN;
    float var = r1[0] * invN - mean * mean;
    float rstd = rsqrtf(var + 1e-5f);

    int h = t & 1;
    float wv[8], bv[8];
#pragma unroll
    for (int j = 0; j < 8; j++) {
        int cg = g * CPG + h * 8 + j;
        wv[j] = gw[cg] * rstd;
        bv[j] = gb[cg] - mean * wv[j];
    }

    for (int u = t; u < 2 * LL; u += 256) {
        int l = u >> 1;
        uint4 pack;
        __half2* ph = (__half2*)&pack;
#pragma unroll
        for (int j = 0; j < 4; j++) {
            float v0 = xp[(size_t)(h * 8 + 2 * j) * LL + l];
            float v1 = xp[(size_t)(h * 8 + 2 * j + 1) * LL + l];
            ph[j] = __floats2half2_rn(v0 * wv[2 * j] + bv[2 * j],
                                      v1 * wv[2 * j + 1] + bv[2 * j + 1]);
        }
        *(uint4*)(g_hT + ((size_t)b * LL + l) * CC + g * CPG + h * 8) = pack;
    }
}

// ---------------------------------------------------------------------------
// Kernel 2: unified QKV GEMM, 128x128 tiles, K-chunk 64, 3-stage ring,
// one sync per iteration; staging issued at loop TOP for max slack.
// ---------------------------------------------------------------------------
#define GP 72
#define GTILE (128 * GP)
#define GSMEM (6 * GTILE * 2)

__global__ void __launch_bounds__(256, 2) qkv_gemm(const float* __restrict__ bias) {
    extern __shared__ __half dyn[];
    __half* As[3] = {dyn, dyn + GTILE, dyn + 2 * GTILE};
    __half* Bs[3] = {dyn + 3 * GTILE, dyn + 4 * GTILE, dyn + 5 * GTILE};

    int id = blockIdx.x;
    bool isqk = id < 1024;
    int b, o0, l0;
    const __half *Asrc, *Bsrc;
    if (isqk) {
        int r = id & 63;
        b = id >> 6;
        l0 = (r & 7) * 128; o0 = (r >> 3) * 128;
        Asrc = g_hT + ((size_t)b * LL + l0) * CC;
        Bsrc = g_wh + (size_t)o0 * CC;
    } else {
        int id2 = id - 1024;
        int r = id2 & 31;
        b = id2 >> 5;
        l0 = (r & 7) * 128; o0 = (r >> 3) * 128;
        Asrc = g_wh + (size_t)(2 * CC + o0) * CC;
        Bsrc = g_hT + ((size_t)b * LL + l0) * CC;
    }
    int t = threadIdx.x, warp = t >> 5, lane = t & 31;
    int g = lane >> 2, tt = lane & 3;
    int wm = warp >> 2, wn = warp & 3;

    int sr = t >> 3, sc = (t & 7) * 8;

    int arow = (lane & 7) + 8 * ((lane >> 3) & 1);
    int acol = 8 * (lane >> 4);
    int brow = (lane & 7) + 8 * ((lane >> 4) & 1);
    int bcol = 8 * ((lane >> 3) & 1);
    unsigned aoff = (unsigned)((wm * 64 + arow) * GP + acol) * 2;
    unsigned boff = (unsigned)((wn * 32 + brow) * GP + bcol) * 2;
    unsigned sA[3], sB[3];
#pragma unroll
    for (int i = 0; i < 3; i++) {
        sA[i] = (unsigned)__cvta_generic_to_shared(As[i]) + aoff;
        sB[i] = (unsigned)__cvta_generic_to_shared(Bs[i]) + boff;
    }

    float acc[4][4][4];
#pragma unroll
    for (int m = 0; m < 4; m++)
#pragma unroll
        for (int n = 0; n < 4; n++)
#pragma unroll
            for (int r = 0; r < 4; r++) acc[m][n][r] = 0.f;

    // prologue: chunks 0 and 1, separate groups
#pragma unroll
    for (int i = 0; i < 4; i++) {
        int rw = sr + i * 32;
        cp16h(&As[0][rw * GP + sc], Asrc + (size_t)rw * CC + sc);
        cp16h(&Bs[0][rw * GP + sc], Bsrc + (size_t)rw * CC + sc);
    }
    cp_commit();
#pragma unroll
    for (int i = 0; i < 4; i++) {
        int rw = sr + i * 32;
        cp16h(&As[1][rw * GP + sc], Asrc + (size_t)rw * CC + 64 + sc);
        cp16h(&Bs[1][rw * GP + sc], Bsrc + (size_t)rw * CC + 64 + sc);
    }
    cp_commit();

    int kcur = 0, kst = 2;
    for (int ic = 0; ic < 8; ic++) {
        cp_wait1();
        __syncthreads();

        // stage chunk ic+2 FIRST (slot's last reader was iter ic-1; fenced above)
        if (ic + 2 < 8) {
            int c0 = (ic + 2) * 64;
#pragma unroll
            for (int i = 0; i < 4; i++) {
                int rw = sr + i * 32;
                cp16h(&As[kst][rw * GP + sc], Asrc + (size_t)rw * CC + c0 + sc);
                cp16h(&Bs[kst][rw * GP + sc], Bsrc + (size_t)rw * CC + c0 + sc);
            }
        }
        cp_commit();

#pragma unroll
        for (int kk = 0; kk < 4; kk++) {
            unsigned a[4][4], bb[2][4];
#pragma unroll
            for (int mm = 0; mm < 4; mm++)
                ldsm4(a[mm], sA[kcur] + (unsigned)(mm * 16 * GP + kk * 16) * 2);
#pragma unroll
            for (int i = 0; i < 2; i++)
                ldsm4(bb[i], sB[kcur] + (unsigned)(i * 16 * GP + kk * 16) * 2);
#pragma unroll
            for (int mm = 0; mm < 4; mm++)
#pragma unroll
                for (int nn = 0; nn < 4; nn++) {
                    unsigned bf[2] = {bb[nn >> 1][2 * (nn & 1)],
                                      bb[nn >> 1][2 * (nn & 1) + 1]};
                    mma_f16(acc[mm][nn], a[mm], bf);
                }
        }

        kcur = (kcur + 1 == 3) ? 0 : kcur + 1;
        kst = (kst + 1 == 3) ? 0 : kst + 1;
    }

    const float QSC = 0.125f * 1.4426950408889634f;
    if (isqk) {
#pragma unroll
        for (int mm = 0; mm < 4; mm++) {
            int l = l0 + wm * 64 + mm * 16 + g;
#pragma unroll
            for (int nn = 0; nn < 4; nn++) {
                int o = o0 + wn * 32 + nn * 8 + 2 * tt;
                int sec = o >> 9, head = (o >> 6) & 7, ch = o & 63;
                float sc2 = (sec == 0) ? QSC : 1.f;
                __half* dst = g_qkT + (((size_t)b * 2 + sec) * 8 + head) * LL * CHH;
                float2 b2 = *(const float2*)&bias[o];
                *(__half2*)&dst[(size_t)l * CHH + ch] =
                    __floats2half2_rn((acc[mm][nn][0] + b2.x) * sc2, (acc[mm][nn][1] + b2.y) * sc2);
                *(__half2*)&dst[(size_t)(l + 8) * CHH + ch] =
                    __floats2half2_rn((acc[mm][nn][2] + b2.x) * sc2, (acc[mm][nn][3] + b2.y) * sc2);
            }
        }
    } else {
        __half* dst = g_v + (size_t)b * CC * LL;
#pragma unroll
        for (int mm = 0; mm < 4; mm++) {
            int o = o0 + wm * 64 + mm * 16 + g;
            float b0 = bias[2 * CC + o], b1 = bias[2 * CC + o + 8];
#pragma unroll
            for (int nn = 0; nn < 4; nn++) {
                int l = l0 + wn * 32 + nn * 8 + 2 * tt;
                *(__half2*)&dst[(size_t)o * LL + l] =
                    __floats2half2_rn(acc[mm][nn][0] + b0, acc[mm][nn][1] + b0);
                *(__half2*)&dst[(size_t)(o + 8) * LL + l] =
                    __floats2half2_rn(acc[mm][nn][2] + b1, acc[mm][nn][3] + b1);
            }
        }
    }
}

// ---------------------------------------------------------------------------
// Kernel 3: flash attention, 3-slot K/V rings, one sync per chunk, staging at
// loop top; exp2/p2 generation interleaved with PV mma per kk-step.
// ---------------------------------------------------------------------------
#define FPAD 72
#define TILE_B (64 * FPAD * 2)
#define FSMEM (6 * TILE_B)          // Q(=V2) + K0..K2 + V0,V1
#define AS_ST 68

__global__ void __launch_bounds__(128, 4) attn_flash(const float* __restrict__ x,
                                                     float* __restrict__ out) {
    extern __shared__ char smc[];
    __half* Qs = (__half*)smc;                       // tile 0 (later: V slot 2)
    __half* Kb[3] = {(__half*)(smc + TILE_B), (__half*)(smc + 2 * TILE_B),
                     (__half*)(smc + 3 * TILE_B)};
    __half* Vb[3] = {(__half*)(smc + 4 * TILE_B), (__half*)(smc + 5 * TILE_B),
                     (__half*)smc};

    int q0 = blockIdx.x;                 // 0..15 (64 queries each)
    int bh = blockIdx.y;                 // 0..127
    int b = bh >> 3, head = bh & 7;
    int t = threadIdx.x, warp = t >> 5, lane = t & 31;
    int g = lane >> 2, tt = lane & 3;

    const __half* qbase = g_qkT + (((size_t)b * 2 + 0) * 8 + head) * LL * CHH;
    const __half* kbase = g_qkT + (((size_t)b * 2 + 1) * 8 + head) * LL * CHH;
    const __half* vbase = g_v + ((size_t)b * CC + head * CHH) * LL;

    int sr = t >> 3, sc = (t & 7) * 8;

    int brow = (lane & 7) + 8 * ((lane >> 4) & 1);
    int bcol = 8 * ((lane >> 3) & 1);
    unsigned kvoff = (unsigned)(brow * FPAD + bcol) * 2;
    unsigned sK[3], sV[3];
#pragma unroll
    for (int i = 0; i < 3; i++) {
        sK[i] = (unsigned)__cvta_generic_to_shared(Kb[i]) + kvoff;
        sV[i] = (unsigned)__cvta_generic_to_shared(Vb[i]) + kvoff;
    }

    // prologue: g0 = {Q, K0, V0}; g1 = {K1, V1}
#pragma unroll
    for (int i = 0; i < 4; i++) {
        int rw = sr + i * 16;
        cp16h(&Qs[rw * FPAD + sc], qbase + (size_t)(q0 * 64 + rw) * CHH + sc);
        cp16h(&Kb[0][rw * FPAD + sc], kbase + (size_t)rw * CHH + sc);
        cp16h(&Vb[0][rw * FPAD + sc], vbase + (size_t)rw * LL + sc);
    }
    cp_commit();
#pragma unroll
    for (int i = 0; i < 4; i++) {
        int rw = sr + i * 16;
        cp16h(&Kb[1][rw * FPAD + sc], kbase + (size_t)(64 + rw) * CHH + sc);
        cp16h(&Vb[1][rw * FPAD + sc], vbase + (size_t)rw * LL + 64 + sc);
    }
    cp_commit();

    float m0 = -INFINITY, m1 = -INFINITY;
    float l0 = 0.f, l1 = 0.f;
    float o[8][4];
#pragma unroll
    for (int j = 0; j < 8; j++)
#pragma unroll
        for (int r = 0; r < 4; r++) o[j][r] = 0.f;

    // pre-loop: g0 done -> load Q fragments (Qs later recycled as V slot 2;
    // first write to it is iter0's staging, ~200+cyc after these LDS issue)
    cp_wait1();
    __syncthreads();
    unsigned qa[4][4];
    {
        const __half* qp = &Qs[(warp * 16 + g) * FPAD];
#pragma unroll
        for (int kk = 0; kk < 4; kk++) {
            const __half* p = qp + kk * 16 + 2 * tt;
            qa[kk][0] = *(const unsigned*)p;
            qa[kk][1] = *(const unsigned*)(p + 8 * FPAD);
            qa[kk][2] = *(const unsigned*)(p + 8);
            qa[kk][3] = *(const unsigned*)(p + 8 * FPAD + 8);
        }
    }

    int kcur = 0, kst = 2;
    for (int ic = 0; ic < 16; ic++) {
        cp_wait1();
        __syncthreads();

        // ---- stage chunk ic+2 FIRST (slot's last reader fenced by top sync) ----
        if (ic + 2 < 16) {
            __half* Kn = Kb[kst];
            __half* Vn = Vb[kst];
            int s0 = (ic + 2) * 64;
#pragma unroll
            for (int i = 0; i < 4; i++) {
                int rw = sr + i * 16;
                cp16h(&Kn[rw * FPAD + sc], kbase + (size_t)(s0 + rw) * CHH + sc);
                cp16h(&Vn[rw * FPAD + sc], vbase + (size_t)rw * LL + s0 + sc);
            }
        }
        cp_commit();

        unsigned K = sK[kcur], V = sV[kcur];

        // ---- S = Q K^T (log2 domain via q pre-scale) ----
        float d[8][4];
#pragma unroll
        for (int j = 0; j < 8; j++)
            d[j][0] = d[j][1] = d[j][2] = d[j][3] = 0.f;
#pragma unroll
        for (int kk = 0; kk < 4; kk++)
#pragma unroll
            for (int i = 0; i < 4; i++) {
                unsigned r[4];
                ldsm4(r, K + (unsigned)(i * 16 * FPAD + kk * 16) * 2);
                unsigned blo[2] = {r[0], r[1]}, bhi[2] = {r[2], r[3]};
                mma_f16(d[2 * i], qa[kk], blo);
                mma_f16(d[2 * i + 1], qa[kk], bhi);
            }

        // ---- row max + rescale factors ----
        float cm0 = -INFINITY, cm1 = -INFINITY;
#pragma unroll
        for (int j = 0; j < 8; j++) {
            cm0 = fmaxf(cm0, fmaxf(d[j][0], d[j][1]));
            cm1 = fmaxf(cm1, fmaxf(d[j][2], d[j][3]));
        }
        cm0 = fmaxf(cm0, __shfl_xor_sync(0xffffffffu, cm0, 1));
        cm0 = fmaxf(cm0, __shfl_xor_sync(0xffffffffu, cm0, 2));
        cm1 = fmaxf(cm1, __shfl_xor_sync(0xffffffffu, cm1, 1));
        cm1 = fmaxf(cm1, __shfl_xor_sync(0xffffffffu, cm1, 2));

        float mn0 = fmaxf(m0, cm0), mn1 = fmaxf(m1, cm1);
        float al0 = exp2f(m0 - mn0), al1 = exp2f(m1 - mn1);
        m0 = mn0; m1 = mn1;

#pragma unroll
        for (int j = 0; j < 8; j++) {
            o[j][0] *= al0; o[j][1] *= al0;
            o[j][2] *= al1; o[j][3] *= al1;
        }

        // ---- interleaved: per kk, generate p2 (MUFU) then PV mma (tensor) ----
        float rs0 = 0.f, rs1 = 0.f;
#pragma unroll
        for (int kk = 0; kk < 4; kk++) {
            unsigned a[4];
            {
                int j = 2 * kk;
                __half2 s01 = __floats2half2_rn(d[j][0] - m0, d[j][1] - m0);
                __half2 s23 = __floats2half2_rn(d[j][2] - m1, d[j][3] - m1);
                a[0] = ex2_f16x2(*(unsigned*)&s01);
                a[1] = ex2_f16x2(*(unsigned*)&s23);
            }
            {
                int j = 2 * kk + 1;
                __half2 s01 = __floats2half2_rn(d[j][0] - m0, d[j][1] - m0);
                __half2 s23 = __floats2half2_rn(d[j][2] - m1, d[j][3] - m1);
                a[2] = ex2_f16x2(*(unsigned*)&s01);
                a[3] = ex2_f16x2(*(unsigned*)&s23);
            }
            float2 f;
            f = __half22float2(*(__half2*)&a[0]); rs0 += f.x + f.y;
            f = __half22float2(*(__half2*)&a[1]); rs1 += f.x + f.y;
            f = __half22float2(*(__half2*)&a[2]); rs0 += f.x + f.y;
            f = __half22float2(*(__half2*)&a[3]); rs1 += f.x + f.y;
#pragma unroll
            for (int i = 0; i < 4; i++) {
                unsigned r[4];
                ldsm4(r, V + (unsigned)(i * 16 * FPAD + kk * 16) * 2);
                unsigned blo[2] = {r[0], r[1]}, bhi[2] = {r[2], r[3]};
                mma_f16(o[2 * i], a, blo);
                mma_f16(o[2 * i + 1], a, bhi);
            }
        }
        l0 = l0 * al0 + rs0;
        l1 = l1 * al1 + rs1;

        kcur = (kcur + 1 == 3) ? 0 : kcur + 1;
        kst = (kst + 1 == 3) ? 0 : kst + 1;
    }

    // deferred l reduction (quad-wide)
    l0 += __shfl_xor_sync(0xffffffffu, l0, 1);
    l0 += __shfl_xor_sync(0xffffffffu, l0, 2);
    l1 += __shfl_xor_sync(0xffffffffu, l1, 1);
    l1 += __shfl_xor_sync(0xffffffffu, l1, 2);

    __syncthreads();   // AS overlaps tiles 0-1; fence iter-15 K/V readers

    // ---- epilogue: A[ch][q] staged in smem, coalesced residual-add ----
    float* AS = (float*)smc;
    float inv0 = 1.f / l0, inv1 = 1.f / l1;
    int qg = warp * 16 + g;
#pragma unroll
    for (int j = 0; j < 8; j++) {
        int ch = j * 8 + 2 * tt;
        AS[ch * AS_ST + qg] = o[j][0] * inv0;
        AS[(ch + 1) * AS_ST + qg] = o[j][1] * inv0;
        AS[ch * AS_ST + qg + 8] = o[j][2] * inv1;
        AS[(ch + 1) * AS_ST + qg + 8] = o[j][3] * inv1;
    }
    __syncthreads();
#pragma unroll
    for (int k = 0; k < 32; k++) {
        int idx = t + k * 128;
        int ch = idx >> 6, q = idx & 63;
        size_t gi = ((size_t)b * CC + head * CHH + ch) * LL + q0 * 64 + q;
        out[gi] = x[gi] + AS[ch * AS_ST + q];
    }
}

// ---------------------------------------------------------------------------
extern "C" void kernel_launch(void* const* d_in, const int* in_sizes, int n_in,
                              void* d_out, int out_size) {
    const float* x = (const float*)d_in[0];
    const float* gn_w = (const float*)d_in[1];
    const float* gn_b = (const float*)d_in[2];
    const float* conv_w = (const float*)d_in[3];
    const float* conv_b = (const float*)d_in[4];
    float* out = (float*)d_out;

    wconv_kernel<<<3 * CC * CC / 512, 256>>>(conv_w);
    gn_kernel<<<BB * GG, 256>>>(x, gn_w, gn_b);

    cudaFuncSetAttribute(qkv_gemm, cudaFuncAttributeMaxDynamicSharedMemorySize,
                         GSMEM);
    qkv_gemm<<<1536, 256, GSMEM>>>(conv_b);

    cudaFuncSetAttribute(attn_flash, cudaFuncAttributeMaxDynamicSharedMemorySize,
                         FSMEM);
    dim3 attn_grid(LL / 64, BB * HEADS);
    attn_flash<<<attn_grid, 128, FSMEM>>>(x, out);
}

// round 15
// speedup vs baseline: 1.0211x; 1.0211x over previous
#include <cuda_runtime.h>
#include <cuda_fp16.h>
#include <cstdint>
#include <math.h>

#define BB 16
#define CC 512
#define LL 1024
#define GG 32
#define CPG 16
#define HEADS 8
#define CHH 64

// Scratch (no allocation allowed)
__device__ __half g_hT[BB * LL * CC];                 // h transposed [b][l][c], fp16
__device__ __half g_wh[3 * CC * CC];                  // conv weight fp16
__device__ __half g_qkT[BB * 2 * HEADS * LL * CHH];   // q,k transposed; q pre-scaled by 0.125*log2(e)
__device__ __half g_v[BB * CC * LL];                  // v natural [b][ch_global][l]

__device__ __forceinline__ void mma_f16(float d[4], const unsigned a[4], const unsigned b[2]) {
    asm volatile(
        "mma.sync.aligned.m16n8k16.row.col.f32.f16.f16.f32 "
        "{%0,%1,%2,%3}, {%4,%5,%6,%7}, {%8,%9}, {%0,%1,%2,%3};"
        : "+f"(d[0]), "+f"(d[1]), "+f"(d[2]), "+f"(d[3])
        : "r"(a[0]), "r"(a[1]), "r"(a[2]), "r"(a[3]),
          "r"(b[0]), "r"(b[1]));
}

__device__ __forceinline__ void ldsm4(unsigned r[4], unsigned saddr) {
    asm volatile("ldmatrix.sync.aligned.m8n8.x4.shared.b16 {%0,%1,%2,%3}, [%4];"
                 : "=r"(r[0]), "=r"(r[1]), "=r"(r[2]), "=r"(r[3]) : "r"(saddr));
}

__device__ __forceinline__ unsigned ex2_f16x2(unsigned v) {
    unsigned r;
    asm("ex2.approx.f16x2 %0, %1;" : "=r"(r) : "r"(v));
    return r;
}

__device__ __forceinline__ void cp16h(__half* dst_smem, const __half* src) {
    unsigned d = (unsigned)__cvta_generic_to_shared(dst_smem);
    asm volatile("cp.async.cg.shared.global [%0], [%1], 16;" :: "r"(d), "l"(src));
}
__device__ __forceinline__ void cp_commit() { asm volatile("cp.async.commit_group;"); }
__device__ __forceinline__ void cp_wait1() { asm volatile("cp.async.wait_group 1;"); }

// ---------------------------------------------------------------------------
// Kernel 0: convert conv weight to fp16.
// ---------------------------------------------------------------------------
__global__ void wconv_kernel(const float* __restrict__ W) {
    int i = blockIdx.x * 256 + threadIdx.x;
    float2 w = ((const float2*)W)[i];
    ((__half2*)g_wh)[i] = __floats2half2_rn(w.x, w.y);
}

// ---------------------------------------------------------------------------
// Kernel 1: GroupNorm(32) -> hT [b][l][c] fp16. One block per (b, g).
// ---------------------------------------------------------------------------
__global__ void gn_kernel(const float* __restrict__ x,
                          const float* __restrict__ gw,
                          const float* __restrict__ gb) {
    int bg = blockIdx.x;
    int b = bg >> 5, g = bg & 31;
    const float* xp = x + ((size_t)b * CC + (size_t)g * CPG) * LL;
    const float4* xp4 = (const float4*)xp;
    int t = threadIdx.x;

    float s = 0.f, ss = 0.f;
    for (int i = t; i < CPG * LL / 4; i += 256) {
        float4 v = xp4[i];
        s += v.x + v.y + v.z + v.w;
        ss += v.x * v.x + v.y * v.y + v.z * v.z + v.w * v.w;
    }
    __shared__ float r0[256], r1[256];
    r0[t] = s; r1[t] = ss;
    __syncthreads();
    for (int o = 128; o > 0; o >>= 1) {
        if (t < o) { r0[t] += r0[t + o]; r1[t] += r1[t + o]; }
        __syncthreads();
    }
    const float invN = 1.f / (CPG * LL);
    float mean = r0[0] * invN;
    float var = r1[0] * invN - mean * mean;
    float rstd = rsqrtf(var + 1e-5f);

    int h = t & 1;
    float wv[8], bv[8];
#pragma unroll
    for (int j = 0; j < 8; j++) {
        int cg = g * CPG + h * 8 + j;
        wv[j] = gw[cg] * rstd;
        bv[j] = gb[cg] - mean * wv[j];
    }

    for (int u = t; u < 2 * LL; u += 256) {
        int l = u >> 1;
        uint4 pack;
        __half2* ph = (__half2*)&pack;
#pragma unroll
        for (int j = 0; j < 4; j++) {
            float v0 = xp[(size_t)(h * 8 + 2 * j) * LL + l];
            float v1 = xp[(size_t)(h * 8 + 2 * j + 1) * LL + l];
            ph[j] = __floats2half2_rn(v0 * wv[2 * j] + bv[2 * j],
                                      v1 * wv[2 * j + 1] + bv[2 * j + 1]);
        }
        *(uint4*)(g_hT + ((size_t)b * LL + l) * CC + g * CPG + h * 8) = pack;
    }
}

// ---------------------------------------------------------------------------
// Kernel 2: unified QKV GEMM (R12-best), 128x128 tiles, K-chunk 64, 3-stage
// ring, one sync per iteration, staging at loop bottom.
// ---------------------------------------------------------------------------
#define GP 72
#define GTILE (128 * GP)
#define GSMEM (6 * GTILE * 2)

__global__ void __launch_bounds__(256, 2) qkv_gemm(const float* __restrict__ bias) {
    extern __shared__ __half dyn[];
    __half* As[3] = {dyn, dyn + GTILE, dyn + 2 * GTILE};
    __half* Bs[3] = {dyn + 3 * GTILE, dyn + 4 * GTILE, dyn + 5 * GTILE};

    int id = blockIdx.x;
    bool isqk = id < 1024;
    int b, o0, l0;
    const __half *Asrc, *Bsrc;
    if (isqk) {
        int r = id & 63;
        b = id >> 6;
        l0 = (r & 7) * 128; o0 = (r >> 3) * 128;
        Asrc = g_hT + ((size_t)b * LL + l0) * CC;
        Bsrc = g_wh + (size_t)o0 * CC;
    } else {
        int id2 = id - 1024;
        int r = id2 & 31;
        b = id2 >> 5;
        l0 = (r & 7) * 128; o0 = (r >> 3) * 128;
        Asrc = g_wh + (size_t)(2 * CC + o0) * CC;
        Bsrc = g_hT + ((size_t)b * LL + l0) * CC;
    }
    int t = threadIdx.x, warp = t >> 5, lane = t & 31;
    int g = lane >> 2, tt = lane & 3;
    int wm = warp >> 2, wn = warp & 3;

    int sr = t >> 3, sc = (t & 7) * 8;

    int arow = (lane & 7) + 8 * ((lane >> 3) & 1);
    int acol = 8 * (lane >> 4);
    int brow = (lane & 7) + 8 * ((lane >> 4) & 1);
    int bcol = 8 * ((lane >> 3) & 1);
    unsigned aoff = (unsigned)((wm * 64 + arow) * GP + acol) * 2;
    unsigned boff = (unsigned)((wn * 32 + brow) * GP + bcol) * 2;
    unsigned sA[3], sB[3];
#pragma unroll
    for (int i = 0; i < 3; i++) {
        sA[i] = (unsigned)__cvta_generic_to_shared(As[i]) + aoff;
        sB[i] = (unsigned)__cvta_generic_to_shared(Bs[i]) + boff;
    }

    float acc[4][4][4];
#pragma unroll
    for (int m = 0; m < 4; m++)
#pragma unroll
        for (int n = 0; n < 4; n++)
#pragma unroll
            for (int r = 0; r < 4; r++) acc[m][n][r] = 0.f;

#pragma unroll
    for (int i = 0; i < 4; i++) {
        int rw = sr + i * 32;
        cp16h(&As[0][rw * GP + sc], Asrc + (size_t)rw * CC + sc);
        cp16h(&Bs[0][rw * GP + sc], Bsrc + (size_t)rw * CC + sc);
    }
    cp_commit();
#pragma unroll
    for (int i = 0; i < 4; i++) {
        int rw = sr + i * 32;
        cp16h(&As[1][rw * GP + sc], Asrc + (size_t)rw * CC + 64 + sc);
        cp16h(&Bs[1][rw * GP + sc], Bsrc + (size_t)rw * CC + 64 + sc);
    }
    cp_commit();

    int kcur = 0, kst = 2;
    for (int ic = 0; ic < 8; ic++) {
        cp_wait1();
        __syncthreads();

#pragma unroll
        for (int kk = 0; kk < 4; kk++) {
            unsigned a[4][4], bb[2][4];
#pragma unroll
            for (int mm = 0; mm < 4; mm++)
                ldsm4(a[mm], sA[kcur] + (unsigned)(mm * 16 * GP + kk * 16) * 2);
#pragma unroll
            for (int i = 0; i < 2; i++)
                ldsm4(bb[i], sB[kcur] + (unsigned)(i * 16 * GP + kk * 16) * 2);
#pragma unroll
            for (int mm = 0; mm < 4; mm++)
#pragma unroll
                for (int nn = 0; nn < 4; nn++) {
                    unsigned bf[2] = {bb[nn >> 1][2 * (nn & 1)],
                                      bb[nn >> 1][2 * (nn & 1) + 1]};
                    mma_f16(acc[mm][nn], a[mm], bf);
                }
        }

        if (ic + 2 < 8) {
            int c0 = (ic + 2) * 64;
#pragma unroll
            for (int i = 0; i < 4; i++) {
                int rw = sr + i * 32;
                cp16h(&As[kst][rw * GP + sc], Asrc + (size_t)rw * CC + c0 + sc);
                cp16h(&Bs[kst][rw * GP + sc], Bsrc + (size_t)rw * CC + c0 + sc);
            }
        }
        cp_commit();

        kcur = (kcur + 1 == 3) ? 0 : kcur + 1;
        kst = (kst + 1 == 3) ? 0 : kst + 1;
    }

    const float QSC = 0.125f * 1.4426950408889634f;
    if (isqk) {
#pragma unroll
        for (int mm = 0; mm < 4; mm++) {
            int l = l0 + wm * 64 + mm * 16 + g;
#pragma unroll
            for (int nn = 0; nn < 4; nn++) {
                int o = o0 + wn * 32 + nn * 8 + 2 * tt;
                int sec = o >> 9, head = (o >> 6) & 7, ch = o & 63;
                float sc2 = (sec == 0) ? QSC : 1.f;
                __half* dst = g_qkT + (((size_t)b * 2 + sec) * 8 + head) * LL * CHH;
                float2 b2 = *(const float2*)&bias[o];
                *(__half2*)&dst[(size_t)l * CHH + ch] =
                    __floats2half2_rn((acc[mm][nn][0] + b2.x) * sc2, (acc[mm][nn][1] + b2.y) * sc2);
                *(__half2*)&dst[(size_t)(l + 8) * CHH + ch] =
                    __floats2half2_rn((acc[mm][nn][2] + b2.x) * sc2, (acc[mm][nn][3] + b2.y) * sc2);
            }
        }
    } else {
        __half* dst = g_v + (size_t)b * CC * LL;
#pragma unroll
        for (int mm = 0; mm < 4; mm++) {
            int o = o0 + wm * 64 + mm * 16 + g;
            float b0 = bias[2 * CC + o], b1 = bias[2 * CC + o + 8];
#pragma unroll
            for (int nn = 0; nn < 4; nn++) {
                int l = l0 + wn * 32 + nn * 8 + 2 * tt;
                *(__half2*)&dst[(size_t)o * LL + l] =
                    __floats2half2_rn(acc[mm][nn][0] + b0, acc[mm][nn][1] + b0);
                *(__half2*)&dst[(size_t)(o + 8) * LL + l] =
                    __floats2half2_rn(acc[mm][nn][2] + b1, acc[mm][nn][3] + b1);
            }
        }
    }
}

// ---------------------------------------------------------------------------
// Kernel 3: flash attention, 256 threads / 128-query tile (8 warps), K/V
// chunks shared by all 8 warps (halved staging + L2 traffic). 3-slot rings,
// one sync per chunk. All 8 tiles fresh (no Q recycling).
// ---------------------------------------------------------------------------
#define FPAD 72
#define TILE_B (64 * FPAD * 2)
#define FSMEM (8 * TILE_B)          // Q(2) + K0..K2 + V0..V2
#define AS_ST 132

__global__ void __launch_bounds__(256, 2) attn_flash(const float* __restrict__ x,
                                                     float* __restrict__ out) {
    extern __shared__ char smc[];
    __half* Qs = (__half*)smc;                       // tiles 0-1: 128 rows
    __half* Kb[3] = {(__half*)(smc + 2 * TILE_B), (__half*)(smc + 3 * TILE_B),
                     (__half*)(smc + 4 * TILE_B)};
    __half* Vb[3] = {(__half*)(smc + 5 * TILE_B), (__half*)(smc + 6 * TILE_B),
                     (__half*)(smc + 7 * TILE_B)};

    int q0 = blockIdx.x;                 // 0..7 (128 queries each)
    int bh = blockIdx.y;                 // 0..127
    int b = bh >> 3, head = bh & 7;
    int t = threadIdx.x, warp = t >> 5, lane = t & 31;
    int g = lane >> 2, tt = lane & 3;

    const __half* qbase = g_qkT + (((size_t)b * 2 + 0) * 8 + head) * LL * CHH;
    const __half* kbase = g_qkT + (((size_t)b * 2 + 1) * 8 + head) * LL * CHH;
    const __half* vbase = g_v + ((size_t)b * CC + head * CHH) * LL;

    int sr = t >> 3, sc = (t & 7) * 8;   // sr in 0..31; K/V rows sr, sr+32

    int brow = (lane & 7) + 8 * ((lane >> 4) & 1);
    int bcol = 8 * ((lane >> 3) & 1);
    unsigned kvoff = (unsigned)(brow * FPAD + bcol) * 2;
    unsigned sK[3], sV[3];
#pragma unroll
    for (int i = 0; i < 3; i++) {
        sK[i] = (unsigned)__cvta_generic_to_shared(Kb[i]) + kvoff;
        sV[i] = (unsigned)__cvta_generic_to_shared(Vb[i]) + kvoff;
    }

    // prologue: g0 = {Q(4/thr), K0, V0}; g1 = {K1, V1}
#pragma unroll
    for (int i = 0; i < 4; i++) {
        int rw = sr + i * 32;
        cp16h(&Qs[rw * FPAD + sc], qbase + (size_t)(q0 * 128 + rw) * CHH + sc);
    }
#pragma unroll
    for (int i = 0; i < 2; i++) {
        int rw = sr + i * 32;
        cp16h(&Kb[0][rw * FPAD + sc], kbase + (size_t)rw * CHH + sc);
        cp16h(&Vb[0][rw * FPAD + sc], vbase + (size_t)rw * LL + sc);
    }
    cp_commit();
#pragma unroll
    for (int i = 0; i < 2; i++) {
        int rw = sr + i * 32;
        cp16h(&Kb[1][rw * FPAD + sc], kbase + (size_t)(64 + rw) * CHH + sc);
        cp16h(&Vb[1][rw * FPAD + sc], vbase + (size_t)rw * LL + 64 + sc);
    }
    cp_commit();

    float m0 = -INFINITY, m1 = -INFINITY;
    float l0 = 0.f, l1 = 0.f;
    float o[8][4];
#pragma unroll
    for (int j = 0; j < 8; j++)
#pragma unroll
        for (int r = 0; r < 4; r++) o[j][r] = 0.f;

    // pre-loop: g0 done -> load Q fragments (each warp its own 16 rows)
    cp_wait1();
    __syncthreads();
    unsigned qa[4][4];
    {
        const __half* qp = &Qs[(warp * 16 + g) * FPAD];
#pragma unroll
        for (int kk = 0; kk < 4; kk++) {
            const __half* p = qp + kk * 16 + 2 * tt;
            qa[kk][0] = *(const unsigned*)p;
            qa[kk][1] = *(const unsigned*)(p + 8 * FPAD);
            qa[kk][2] = *(const unsigned*)(p + 8);
            qa[kk][3] = *(const unsigned*)(p + 8 * FPAD + 8);
        }
    }

    int kcur = 0, kst = 2;
    for (int ic = 0; ic < 16; ic++) {
        cp_wait1();
        __syncthreads();

        unsigned K = sK[kcur], V = sV[kcur];

        // ---- S = Q K^T (log2 domain via q pre-scale) ----
        float d[8][4];
#pragma unroll
        for (int j = 0; j < 8; j++)
            d[j][0] = d[j][1] = d[j][2] = d[j][3] = 0.f;
#pragma unroll
        for (int kk = 0; kk < 4; kk++)
#pragma unroll
            for (int i = 0; i < 4; i++) {
                unsigned r[4];
                ldsm4(r, K + (unsigned)(i * 16 * FPAD + kk * 16) * 2);
                unsigned blo[2] = {r[0], r[1]}, bhi[2] = {r[2], r[3]};
                mma_f16(d[2 * i], qa[kk], blo);
                mma_f16(d[2 * i + 1], qa[kk], bhi);
            }

        // ---- online softmax (exp2 domain, f16x2 MUFU) ----
        float cm0 = -INFINITY, cm1 = -INFINITY;
#pragma unroll
        for (int j = 0; j < 8; j++) {
            cm0 = fmaxf(cm0, fmaxf(d[j][0], d[j][1]));
            cm1 = fmaxf(cm1, fmaxf(d[j][2], d[j][3]));
        }
        cm0 = fmaxf(cm0, __shfl_xor_sync(0xffffffffu, cm0, 1));
        cm0 = fmaxf(cm0, __shfl_xor_sync(0xffffffffu, cm0, 2));
        cm1 = fmaxf(cm1, __shfl_xor_sync(0xffffffffu, cm1, 1));
        cm1 = fmaxf(cm1, __shfl_xor_sync(0xffffffffu, cm1, 2));

        float mn0 = fmaxf(m0, cm0), mn1 = fmaxf(m1, cm1);
        float al0 = exp2f(m0 - mn0), al1 = exp2f(m1 - mn1);
        m0 = mn0; m1 = mn1;

        float rs0 = 0.f, rs1 = 0.f;
        unsigned p2[8][2];
#pragma unroll
        for (int j = 0; j < 8; j++) {
            __half2 s01 = __floats2half2_rn(d[j][0] - m0, d[j][1] - m0);
            __half2 s23 = __floats2half2_rn(d[j][2] - m1, d[j][3] - m1);
            p2[j][0] = ex2_f16x2(*(unsigned*)&s01);
            p2[j][1] = ex2_f16x2(*(unsigned*)&s23);
            float2 f01 = __half22float2(*(__half2*)&p2[j][0]);
            float2 f23 = __half22float2(*(__half2*)&p2[j][1]);
            rs0 += f01.x + f01.y;
            rs1 += f23.x + f23.y;
        }
        l0 = l0 * al0 + rs0;
        l1 = l1 * al1 + rs1;

#pragma unroll
        for (int j = 0; j < 8; j++) {
            o[j][0] *= al0; o[j][1] *= al0;
            o[j][2] *= al1; o[j][3] *= al1;
        }

        // ---- O += P V^T ----
#pragma unroll
        for (int kk = 0; kk < 4; kk++) {
            unsigned a[4] = {p2[2 * kk][0], p2[2 * kk][1],
                             p2[2 * kk + 1][0], p2[2 * kk + 1][1]};
#pragma unroll
            for (int i = 0; i < 4; i++) {
                unsigned r[4];
                ldsm4(r, V + (unsigned)(i * 16 * FPAD + kk * 16) * 2);
                unsigned blo[2] = {r[0], r[1]}, bhi[2] = {r[2], r[3]};
                mma_f16(o[2 * i], a, blo);
                mma_f16(o[2 * i + 1], a, bhi);
            }
        }

        // ---- stage chunk ic+2 into slot kst (last read iter ic-1) ----
        if (ic + 2 < 16) {
            __half* Kn = Kb[kst];
            __half* Vn = Vb[kst];
            int s0 = (ic + 2) * 64;
#pragma unroll
            for (int i = 0; i < 2; i++) {
                int rw = sr + i * 32;
                cp16h(&Kn[rw * FPAD + sc], kbase + (size_t)(s0 + rw) * CHH + sc);
                cp16h(&Vn[rw * FPAD + sc], vbase + (size_t)rw * LL + s0 + sc);
            }
        }
        cp_commit();

        kcur = (kcur + 1 == 3) ? 0 : kcur + 1;
        kst = (kst + 1 == 3) ? 0 : kst + 1;
    }

    // deferred l reduction (quad-wide)
    l0 += __shfl_xor_sync(0xffffffffu, l0, 1);
    l0 += __shfl_xor_sync(0xffffffffu, l0, 2);
    l1 += __shfl_xor_sync(0xffffffffu, l1, 1);
    l1 += __shfl_xor_sync(0xffffffffu, l1, 2);

    __syncthreads();   // AS overlaps Q/K tiles; fence iter-15 readers

    // ---- epilogue: A[ch][q] staged in smem, coalesced residual-add ----
    float* AS = (float*)smc;   // 64 x 132 fp32 = 33.8KB
    float inv0 = 1.f / l0, inv1 = 1.f / l1;
    int qg = warp * 16 + g;
#pragma unroll
    for (int j = 0; j < 8; j++) {
        int ch = j * 8 + 2 * tt;
        AS[ch * AS_ST + qg] = o[j][0] * inv0;
        AS[(ch + 1) * AS_ST + qg] = o[j][1] * inv0;
        AS[ch * AS_ST + qg + 8] = o[j][2] * inv1;
        AS[(ch + 1) * AS_ST + qg + 8] = o[j][3] * inv1;
    }
    __syncthreads();
#pragma unroll
    for (int k = 0; k < 32; k++) {
        int idx = t + k * 256;
        int ch = idx >> 7, q = idx & 127;
        size_t gi = ((size_t)b * CC + head * CHH + ch) * LL + q0 * 128 + q;
        out[gi] = x[gi] + AS[ch * AS_ST + q];
    }
}

// ---------------------------------------------------------------------------
extern "C" void kernel_launch(void* const* d_in, const int* in_sizes, int n_in,
                              void* d_out, int out_size) {
    const float* x = (const float*)d_in[0];
    const float* gn_w = (const float*)d_in[1];
    const float* gn_b = (const float*)d_in[2];
    const float* conv_w = (const float*)d_in[3];
    const float* conv_b = (const float*)d_in[4];
    float* out = (float*)d_out;

    wconv_kernel<<<3 * CC * CC / 512, 256>>>(conv_w);
    gn_kernel<<<BB * GG, 256>>>(x, gn_w, gn_b);

    cudaFuncSetAttribute(qkv_gemm, cudaFuncAttributeMaxDynamicSharedMemorySize,
                         GSMEM);
    qkv_gemm<<<1536, 256, GSMEM>>>(conv_b);

    cudaFuncSetAttribute(attn_flash, cudaFuncAttributeMaxDynamicSharedMemorySize,
                         FSMEM);
    dim3 attn_grid(LL / 128, BB * HEADS);
    attn_flash<<<attn_grid, 256, FSMEM>>>(x, out);
}

// round 16
// speedup vs baseline: 1.0544x; 1.0326x over previous
#include <cuda_runtime.h>
#include <cuda_fp16.h>
#include <cstdint>
#include <math.h>

#define BB 16
#define CC 512
#define LL 1024
#define GG 32
#define CPG 16
#define HEADS 8
#define CHH 64

// Scratch (no allocation allowed)
__device__ __half g_hT[BB * LL * CC];                 // h transposed [b][l][c], fp16
__device__ __half g_wh[3 * CC * CC];                  // conv weight fp16
__device__ __half g_qkT[BB * 2 * HEADS * LL * CHH];   // q,k transposed; q pre-scaled by 0.125*log2(e)
__device__ __half g_v[BB * CC * LL];                  // v natural [b][ch_global][l]

__device__ __forceinline__ void mma_f16(float d[4], const unsigned a[4], const unsigned b[2]) {
    asm volatile(
        "mma.sync.aligned.m16n8k16.row.col.f32.f16.f16.f32 "
        "{%0,%1,%2,%3}, {%4,%5,%6,%7}, {%8,%9}, {%0,%1,%2,%3};"
        : "+f"(d[0]), "+f"(d[1]), "+f"(d[2]), "+f"(d[3])
        : "r"(a[0]), "r"(a[1]), "r"(a[2]), "r"(a[3]),
          "r"(b[0]), "r"(b[1]));
}

__device__ __forceinline__ void ldsm4(unsigned r[4], unsigned saddr) {
    asm volatile("ldmatrix.sync.aligned.m8n8.x4.shared.b16 {%0,%1,%2,%3}, [%4];"
                 : "=r"(r[0]), "=r"(r[1]), "=r"(r[2]), "=r"(r[3]) : "r"(saddr));
}

__device__ __forceinline__ unsigned ex2_f16x2(unsigned v) {
    unsigned r;
    asm("ex2.approx.f16x2 %0, %1;" : "=r"(r) : "r"(v));
    return r;
}

__device__ __forceinline__ void cp16h(__half* dst_smem, const __half* src) {
    unsigned d = (unsigned)__cvta_generic_to_shared(dst_smem);
    asm volatile("cp.async.cg.shared.global [%0], [%1], 16;" :: "r"(d), "l"(src));
}
__device__ __forceinline__ void cp_commit() { asm volatile("cp.async.commit_group;"); }
__device__ __forceinline__ void cp_wait1() { asm volatile("cp.async.wait_group 1;"); }

// ---------------------------------------------------------------------------
// Kernel 0: convert conv weight to fp16.
// ---------------------------------------------------------------------------
__global__ void wconv_kernel(const float* __restrict__ W) {
    int i = blockIdx.x * 256 + threadIdx.x;
    float2 w = ((const float2*)W)[i];
    ((__half2*)g_wh)[i] = __floats2half2_rn(w.x, w.y);
}

// ---------------------------------------------------------------------------
// Kernel 1: GroupNorm(32) -> hT [b][l][c] fp16. One block per (b, g).
// ---------------------------------------------------------------------------
__global__ void gn_kernel(const float* __restrict__ x,
                          const float* __restrict__ gw,
                          const float* __restrict__ gb) {
    int bg = blockIdx.x;
    int b = bg >> 5, g = bg & 31;
    const float* xp = x + ((size_t)b * CC + (size_t)g * CPG) * LL;
    const float4* xp4 = (const float4*)xp;
    int t = threadIdx.x;

    float s = 0.f, ss = 0.f;
    for (int i = t; i < CPG * LL / 4; i += 256) {
        float4 v = xp4[i];
        s += v.x + v.y + v.z + v.w;
        ss += v.x * v.x + v.y * v.y + v.z * v.z + v.w * v.w;
    }
    __shared__ float r0[256], r1[256];
    r0[t] = s; r1[t] = ss;
    __syncthreads();
    for (int o = 128; o > 0; o >>= 1) {
        if (t < o) { r0[t] += r0[t + o]; r1[t] += r1[t + o]; }
        __syncthreads();
    }
    const float invN = 1.f / (CPG * LL);
    float mean = r0[0] * invN;
    float var = r1[0] * invN - mean * mean;
    float rstd = rsqrtf(var + 1e-5f);

    int h = t & 1;
    float wv[8], bv[8];
#pragma unroll
    for (int j = 0; j < 8; j++) {
        int cg = g * CPG + h * 8 + j;
        wv[j] = gw[cg] * rstd;
        bv[j] = gb[cg] - mean * wv[j];
    }

    for (int u = t; u < 2 * LL; u += 256) {
        int l = u >> 1;
        uint4 pack;
        __half2* ph = (__half2*)&pack;
#pragma unroll
        for (int j = 0; j < 4; j++) {
            float v0 = xp[(size_t)(h * 8 + 2 * j) * LL + l];
            float v1 = xp[(size_t)(h * 8 + 2 * j + 1) * LL + l];
            ph[j] = __floats2half2_rn(v0 * wv[2 * j] + bv[2 * j],
                                      v1 * wv[2 * j + 1] + bv[2 * j + 1]);
        }
        *(uint4*)(g_hT + ((size_t)b * LL + l) * CC + g * CPG + h * 8) = pack;
    }
}

// ---------------------------------------------------------------------------
// Kernel 2: unified QKV GEMM (R12-best), 128x128 tiles, K-chunk 64, 3-stage
// ring, one sync per iteration.
// ---------------------------------------------------------------------------
#define GP 72
#define GTILE (128 * GP)
#define GSMEM (6 * GTILE * 2)

__global__ void __launch_bounds__(256, 2) qkv_gemm(const float* __restrict__ bias) {
    extern __shared__ __half dyn[];
    __half* As[3] = {dyn, dyn + GTILE, dyn + 2 * GTILE};
    __half* Bs[3] = {dyn + 3 * GTILE, dyn + 4 * GTILE, dyn + 5 * GTILE};

    int id = blockIdx.x;
    bool isqk = id < 1024;
    int b, o0, l0;
    const __half *Asrc, *Bsrc;
    if (isqk) {
        int r = id & 63;
        b = id >> 6;
        l0 = (r & 7) * 128; o0 = (r >> 3) * 128;
        Asrc = g_hT + ((size_t)b * LL + l0) * CC;
        Bsrc = g_wh + (size_t)o0 * CC;
    } else {
        int id2 = id - 1024;
        int r = id2 & 31;
        b = id2 >> 5;
        l0 = (r & 7) * 128; o0 = (r >> 3) * 128;
        Asrc = g_wh + (size_t)(2 * CC + o0) * CC;
        Bsrc = g_hT + ((size_t)b * LL + l0) * CC;
    }
    int t = threadIdx.x, warp = t >> 5, lane = t & 31;
    int g = lane >> 2, tt = lane & 3;
    int wm = warp >> 2, wn = warp & 3;

    int sr = t >> 3, sc = (t & 7) * 8;

    int arow = (lane & 7) + 8 * ((lane >> 3) & 1);
    int acol = 8 * (lane >> 4);
    int brow = (lane & 7) + 8 * ((lane >> 4) & 1);
    int bcol = 8 * ((lane >> 3) & 1);
    unsigned aoff = (unsigned)((wm * 64 + arow) * GP + acol) * 2;
    unsigned boff = (unsigned)((wn * 32 + brow) * GP + bcol) * 2;
    unsigned sA[3], sB[3];
#pragma unroll
    for (int i = 0; i < 3; i++) {
        sA[i] = (unsigned)__cvta_generic_to_shared(As[i]) + aoff;
        sB[i] = (unsigned)__cvta_generic_to_shared(Bs[i]) + boff;
    }

    float acc[4][4][4];
#pragma unroll
    for (int m = 0; m < 4; m++)
#pragma unroll
        for (int n = 0; n < 4; n++)
#pragma unroll
            for (int r = 0; r < 4; r++) acc[m][n][r] = 0.f;

#pragma unroll
    for (int i = 0; i < 4; i++) {
        int rw = sr + i * 32;
        cp16h(&As[0][rw * GP + sc], Asrc + (size_t)rw * CC + sc);
        cp16h(&Bs[0][rw * GP + sc], Bsrc + (size_t)rw * CC + sc);
    }
    cp_commit();
#pragma unroll
    for (int i = 0; i < 4; i++) {
        int rw = sr + i * 32;
        cp16h(&As[1][rw * GP + sc], Asrc + (size_t)rw * CC + 64 + sc);
        cp16h(&Bs[1][rw * GP + sc], Bsrc + (size_t)rw * CC + 64 + sc);
    }
    cp_commit();

    int kcur = 0, kst = 2;
    for (int ic = 0; ic < 8; ic++) {
        cp_wait1();
        __syncthreads();

#pragma unroll
        for (int kk = 0; kk < 4; kk++) {
            unsigned a[4][4], bb[2][4];
#pragma unroll
            for (int mm = 0; mm < 4; mm++)
                ldsm4(a[mm], sA[kcur] + (unsigned)(mm * 16 * GP + kk * 16) * 2);
#pragma unroll
            for (int i = 0; i < 2; i++)
                ldsm4(bb[i], sB[kcur] + (unsigned)(i * 16 * GP + kk * 16) * 2);
#pragma unroll
            for (int mm = 0; mm < 4; mm++)
#pragma unroll
                for (int nn = 0; nn < 4; nn++) {
                    unsigned bf[2] = {bb[nn >> 1][2 * (nn & 1)],
                                      bb[nn >> 1][2 * (nn & 1) + 1]};
                    mma_f16(acc[mm][nn], a[mm], bf);
                }
        }

        if (ic + 2 < 8) {
            int c0 = (ic + 2) * 64;
#pragma unroll
            for (int i = 0; i < 4; i++) {
                int rw = sr + i * 32;
                cp16h(&As[kst][rw * GP + sc], Asrc + (size_t)rw * CC + c0 + sc);
                cp16h(&Bs[kst][rw * GP + sc], Bsrc + (size_t)rw * CC + c0 + sc);
            }
        }
        cp_commit();

        kcur = (kcur + 1 == 3) ? 0 : kcur + 1;
        kst = (kst + 1 == 3) ? 0 : kst + 1;
    }

    const float QSC = 0.125f * 1.4426950408889634f;
    if (isqk) {
#pragma unroll
        for (int mm = 0; mm < 4; mm++) {
            int l = l0 + wm * 64 + mm * 16 + g;
#pragma unroll
            for (int nn = 0; nn < 4; nn++) {
                int o = o0 + wn * 32 + nn * 8 + 2 * tt;
                int sec = o >> 9, head = (o >> 6) & 7, ch = o & 63;
                float sc2 = (sec == 0) ? QSC : 1.f;
                __half* dst = g_qkT + (((size_t)b * 2 + sec) * 8 + head) * LL * CHH;
                float2 b2 = *(const float2*)&bias[o];
                *(__half2*)&dst[(size_t)l * CHH + ch] =
                    __floats2half2_rn((acc[mm][nn][0] + b2.x) * sc2, (acc[mm][nn][1] + b2.y) * sc2);
                *(__half2*)&dst[(size_t)(l + 8) * CHH + ch] =
                    __floats2half2_rn((acc[mm][nn][2] + b2.x) * sc2, (acc[mm][nn][3] + b2.y) * sc2);
            }
        }
    } else {
        __half* dst = g_v + (size_t)b * CC * LL;
#pragma unroll
        for (int mm = 0; mm < 4; mm++) {
            int o = o0 + wm * 64 + mm * 16 + g;
            float b0 = bias[2 * CC + o], b1 = bias[2 * CC + o + 8];
#pragma unroll
            for (int nn = 0; nn < 4; nn++) {
                int l = l0 + wn * 32 + nn * 8 + 2 * tt;
                *(__half2*)&dst[(size_t)o * LL + l] =
                    __floats2half2_rn(acc[mm][nn][0] + b0, acc[mm][nn][1] + b0);
                *(__half2*)&dst[(size_t)(o + 8) * LL + l] =
                    __floats2half2_rn(acc[mm][nn][2] + b1, acc[mm][nn][3] + b1);
            }
        }
    }
}

// ---------------------------------------------------------------------------
// Kernel 3: flash attention, 256 threads / 128-query tile. Row-sum l computed
// on the tensor core via an all-ones B fragment (65th output channel).
// ---------------------------------------------------------------------------
#define FPAD 72
#define TILE_B (64 * FPAD * 2)
#define FSMEM (8 * TILE_B)          // Q(2) + K0..K2 + V0..V2
#define AS_ST 132

__global__ void __launch_bounds__(256, 2) attn_flash(const float* __restrict__ x,
                                                     float* __restrict__ out) {
    extern __shared__ char smc[];
    __half* Qs = (__half*)smc;                       // tiles 0-1: 128 rows
    __half* Kb[3] = {(__half*)(smc + 2 * TILE_B), (__half*)(smc + 3 * TILE_B),
                     (__half*)(smc + 4 * TILE_B)};
    __half* Vb[3] = {(__half*)(smc + 5 * TILE_B), (__half*)(smc + 6 * TILE_B),
                     (__half*)(smc + 7 * TILE_B)};

    int q0 = blockIdx.x;                 // 0..7 (128 queries each)
    int bh = blockIdx.y;                 // 0..127
    int b = bh >> 3, head = bh & 7;
    int t = threadIdx.x, warp = t >> 5, lane = t & 31;
    int g = lane >> 2, tt = lane & 3;

    const __half* qbase = g_qkT + (((size_t)b * 2 + 0) * 8 + head) * LL * CHH;
    const __half* kbase = g_qkT + (((size_t)b * 2 + 1) * 8 + head) * LL * CHH;
    const __half* vbase = g_v + ((size_t)b * CC + head * CHH) * LL;

    int sr = t >> 3, sc = (t & 7) * 8;   // K/V rows sr, sr+32

    int brow = (lane & 7) + 8 * ((lane >> 4) & 1);
    int bcol = 8 * ((lane >> 3) & 1);
    unsigned kvoff = (unsigned)(brow * FPAD + bcol) * 2;
    unsigned sK[3], sV[3];
#pragma unroll
    for (int i = 0; i < 3; i++) {
        sK[i] = (unsigned)__cvta_generic_to_shared(Kb[i]) + kvoff;
        sV[i] = (unsigned)__cvta_generic_to_shared(Vb[i]) + kvoff;
    }

    // prologue: g0 = {Q(4/thr), K0, V0}; g1 = {K1, V1}
#pragma unroll
    for (int i = 0; i < 4; i++) {
        int rw = sr + i * 32;
        cp16h(&Qs[rw * FPAD + sc], qbase + (size_t)(q0 * 128 + rw) * CHH + sc);
    }
#pragma unroll
    for (int i = 0; i < 2; i++) {
        int rw = sr + i * 32;
        cp16h(&Kb[0][rw * FPAD + sc], kbase + (size_t)rw * CHH + sc);
        cp16h(&Vb[0][rw * FPAD + sc], vbase + (size_t)rw * LL + sc);
    }
    cp_commit();
#pragma unroll
    for (int i = 0; i < 2; i++) {
        int rw = sr + i * 32;
        cp16h(&Kb[1][rw * FPAD + sc], kbase + (size_t)(64 + rw) * CHH + sc);
        cp16h(&Vb[1][rw * FPAD + sc], vbase + (size_t)rw * LL + 64 + sc);
    }
    cp_commit();

    float m0 = -INFINITY, m1 = -INFINITY;
    float lacc[4] = {0.f, 0.f, 0.f, 0.f};   // tensor-core row sums
    float o[8][4];
#pragma unroll
    for (int j = 0; j < 8; j++)
#pragma unroll
        for (int r = 0; r < 4; r++) o[j][r] = 0.f;

    const unsigned ONES2 = 0x3C003C00u;      // {1.0h, 1.0h}

    // pre-loop: g0 done -> load Q fragments (each warp its own 16 rows)
    cp_wait1();
    __syncthreads();
    unsigned qa[4][4];
    {
        const __half* qp = &Qs[(warp * 16 + g) * FPAD];
#pragma unroll
        for (int kk = 0; kk < 4; kk++) {
            const __half* p = qp + kk * 16 + 2 * tt;
            qa[kk][0] = *(const unsigned*)p;
            qa[kk][1] = *(const unsigned*)(p + 8 * FPAD);
            qa[kk][2] = *(const unsigned*)(p + 8);
            qa[kk][3] = *(const unsigned*)(p + 8 * FPAD + 8);
        }
    }

    int kcur = 0, kst = 2;
    for (int ic = 0; ic < 16; ic++) {
        cp_wait1();
        __syncthreads();

        unsigned K = sK[kcur], V = sV[kcur];

        // ---- S = Q K^T (log2 domain via q pre-scale) ----
        float d[8][4];
#pragma unroll
        for (int j = 0; j < 8; j++)
            d[j][0] = d[j][1] = d[j][2] = d[j][3] = 0.f;
#pragma unroll
        for (int kk = 0; kk < 4; kk++)
#pragma unroll
            for (int i = 0; i < 4; i++) {
                unsigned r[4];
                ldsm4(r, K + (unsigned)(i * 16 * FPAD + kk * 16) * 2);
                unsigned blo[2] = {r[0], r[1]}, bhi[2] = {r[2], r[3]};
                mma_f16(d[2 * i], qa[kk], blo);
                mma_f16(d[2 * i + 1], qa[kk], bhi);
            }

        // ---- online softmax (exp2 domain, f16x2 MUFU) ----
        float cm0 = -INFINITY, cm1 = -INFINITY;
#pragma unroll
        for (int j = 0; j < 8; j++) {
            cm0 = fmaxf(cm0, fmaxf(d[j][0], d[j][1]));
            cm1 = fmaxf(cm1, fmaxf(d[j][2], d[j][3]));
        }
        cm0 = fmaxf(cm0, __shfl_xor_sync(0xffffffffu, cm0, 1));
        cm0 = fmaxf(cm0, __shfl_xor_sync(0xffffffffu, cm0, 2));
        cm1 = fmaxf(cm1, __shfl_xor_sync(0xffffffffu, cm1, 1));
        cm1 = fmaxf(cm1, __shfl_xor_sync(0xffffffffu, cm1, 2));

        float mn0 = fmaxf(m0, cm0), mn1 = fmaxf(m1, cm1);
        float al0 = exp2f(m0 - mn0), al1 = exp2f(m1 - mn1);
        m0 = mn0; m1 = mn1;

        unsigned p2[8][2];
#pragma unroll
        for (int j = 0; j < 8; j++) {
            __half2 s01 = __floats2half2_rn(d[j][0] - m0, d[j][1] - m0);
            __half2 s23 = __floats2half2_rn(d[j][2] - m1, d[j][3] - m1);
            p2[j][0] = ex2_f16x2(*(unsigned*)&s01);
            p2[j][1] = ex2_f16x2(*(unsigned*)&s23);
        }

        // rescale O and l accumulators
#pragma unroll
        for (int j = 0; j < 8; j++) {
            o[j][0] *= al0; o[j][1] *= al0;
            o[j][2] *= al1; o[j][3] *= al1;
        }
        lacc[0] *= al0; lacc[1] *= al0;
        lacc[2] *= al1; lacc[3] *= al1;

        // ---- O += P V^T ; l += P @ ones (tensor-core row sum) ----
#pragma unroll
        for (int kk = 0; kk < 4; kk++) {
            unsigned a[4] = {p2[2 * kk][0], p2[2 * kk][1],
                             p2[2 * kk + 1][0], p2[2 * kk + 1][1]};
#pragma unroll
            for (int i = 0; i < 4; i++) {
                unsigned r[4];
                ldsm4(r, V + (unsigned)(i * 16 * FPAD + kk * 16) * 2);
                unsigned blo[2] = {r[0], r[1]}, bhi[2] = {r[2], r[3]};
                mma_f16(o[2 * i], a, blo);
                mma_f16(o[2 * i + 1], a, bhi);
            }
            unsigned bones[2] = {ONES2, ONES2};
            mma_f16(lacc, a, bones);
        }

        // ---- stage chunk ic+2 into slot kst (last read iter ic-1) ----
        if (ic + 2 < 16) {
            __half* Kn = Kb[kst];
            __half* Vn = Vb[kst];
            int s0 = (ic + 2) * 64;
#pragma unroll
            for (int i = 0; i < 2; i++) {
                int rw = sr + i * 32;
                cp16h(&Kn[rw * FPAD + sc], kbase + (size_t)(s0 + rw) * CHH + sc);
                cp16h(&Vn[rw * FPAD + sc], vbase + (size_t)rw * LL + s0 + sc);
            }
        }
        cp_commit();

        kcur = (kcur + 1 == 3) ? 0 : kcur + 1;
        kst = (kst + 1 == 3) ? 0 : kst + 1;
    }

    __syncthreads();   // AS overlaps Q/K tiles; fence iter-15 readers

    // ---- epilogue: A[ch][q] staged in smem, coalesced residual-add ----
    float* AS = (float*)smc;   // 64 x 132 fp32 = 33.8KB
    float inv0 = 1.f / lacc[0], inv1 = 1.f / lacc[2];
    int qg = warp * 16 + g;
#pragma unroll
    for (int j = 0; j < 8; j++) {
        int ch = j * 8 + 2 * tt;
        AS[ch * AS_ST + qg] = o[j][0] * inv0;
        AS[(ch + 1) * AS_ST + qg] = o[j][1] * inv0;
        AS[ch * AS_ST + qg + 8] = o[j][2] * inv1;
        AS[(ch + 1) * AS_ST + qg + 8] = o[j][3] * inv1;
    }
    __syncthreads();
#pragma unroll
    for (int k = 0; k < 32; k++) {
        int idx = t + k * 256;
        int ch = idx >> 7, q = idx & 127;
        size_t gi = ((size_t)b * CC + head * CHH + ch) * LL + q0 * 128 + q;
        out[gi] = x[gi] + AS[ch * AS_ST + q];
    }
}

// ---------------------------------------------------------------------------
extern "C" void kernel_launch(void* const* d_in, const int* in_sizes, int n_in,
                              void* d_out, int out_size) {
    const float* x = (const float*)d_in[0];
    const float* gn_w = (const float*)d_in[1];
    const float* gn_b = (const float*)d_in[2];
    const float* conv_w = (const float*)d_in[3];
    const float* conv_b = (const float*)d_in[4];
    float* out = (float*)d_out;

    wconv_kernel<<<3 * CC * CC / 512, 256>>>(conv_w);
    gn_kernel<<<BB * GG, 256>>>(x, gn_w, gn_b);

    cudaFuncSetAttribute(qkv_gemm, cudaFuncAttributeMaxDynamicSharedMemorySize,
                         GSMEM);
    qkv_gemm<<<1536, 256, GSMEM>>>(conv_b);

    cudaFuncSetAttribute(attn_flash, cudaFuncAttributeMaxDynamicSharedMemorySize,
                         FSMEM);
    dim3 attn_grid(LL / 128, BB * HEADS);
    attn_flash<<<attn_grid, 256, FSMEM>>>(x, out);
}

// round 17
// speedup vs baseline: 1.0789x; 1.0233x over previous
#include <cuda_runtime.h>
#include <cuda_fp16.h>
#include <cstdint>
#include <math.h>

#define BB 16
#define CC 512
#define LL 1024
#define GG 32
#define CPG 16
#define HEADS 8
#define CHH 64

// Scratch (no allocation allowed)
__device__ __half g_hT[BB * LL * CC];                 // h transposed [b][l][c], fp16
__device__ __half g_wh[3 * CC * CC];                  // conv weight fp16
__device__ __half g_qkT[BB * 2 * HEADS * LL * CHH];   // q,k transposed; q pre-scaled by 0.125*log2(e)
__device__ __half g_v[BB * CC * LL];                  // v natural [b][ch_global][l]

__device__ __forceinline__ void mma_f16(float d[4], const unsigned a[4], const unsigned b[2]) {
    asm volatile(
        "mma.sync.aligned.m16n8k16.row.col.f32.f16.f16.f32 "
        "{%0,%1,%2,%3}, {%4,%5,%6,%7}, {%8,%9}, {%0,%1,%2,%3};"
        : "+f"(d[0]), "+f"(d[1]), "+f"(d[2]), "+f"(d[3])
        : "r"(a[0]), "r"(a[1]), "r"(a[2]), "r"(a[3]),
          "r"(b[0]), "r"(b[1]));
}

__device__ __forceinline__ void ldsm4(unsigned r[4], unsigned saddr) {
    asm volatile("ldmatrix.sync.aligned.m8n8.x4.shared.b16 {%0,%1,%2,%3}, [%4];"
                 : "=r"(r[0]), "=r"(r[1]), "=r"(r[2]), "=r"(r[3]) : "r"(saddr));
}

__device__ __forceinline__ unsigned ex2_f16x2(unsigned v) {
    unsigned r;
    asm("ex2.approx.f16x2 %0, %1;" : "=r"(r) : "r"(v));
    return r;
}

__device__ __forceinline__ void cp16h(__half* dst_smem, const __half* src) {
    unsigned d = (unsigned)__cvta_generic_to_shared(dst_smem);
    asm volatile("cp.async.cg.shared.global [%0], [%1], 16;" :: "r"(d), "l"(src));
}
__device__ __forceinline__ void cp_commit() { asm volatile("cp.async.commit_group;"); }
__device__ __forceinline__ void cp_wait1() { asm volatile("cp.async.wait_group 1;"); }

// ---------------------------------------------------------------------------
// Kernel 0: convert conv weight to fp16.
// ---------------------------------------------------------------------------
__global__ void wconv_kernel(const float* __restrict__ W) {
    int i = blockIdx.x * 256 + threadIdx.x;
    float2 w = ((const float2*)W)[i];
    ((__half2*)g_wh)[i] = __floats2half2_rn(w.x, w.y);
}

// ---------------------------------------------------------------------------
// Kernel 1: GroupNorm(32) -> hT [b][l][c] fp16. One block per (b, g).
// ---------------------------------------------------------------------------
__global__ void gn_kernel(const float* __restrict__ x,
                          const float* __restrict__ gw,
                          const float* __restrict__ gb) {
    int bg = blockIdx.x;
    int b = bg >> 5, g = bg & 31;
    const float* xp = x + ((size_t)b * CC + (size_t)g * CPG) * LL;
    const float4* xp4 = (const float4*)xp;
    int t = threadIdx.x;

    float s = 0.f, ss = 0.f;
    for (int i = t; i < CPG * LL / 4; i += 256) {
        float4 v = xp4[i];
        s += v.x + v.y + v.z + v.w;
        ss += v.x * v.x + v.y * v.y + v.z * v.z + v.w * v.w;
    }
    __shared__ float r0[256], r1[256];
    r0[t] = s; r1[t] = ss;
    __syncthreads();
    for (int o = 128; o > 0; o >>= 1) {
        if (t < o) { r0[t] += r0[t + o]; r1[t] += r1[t + o]; }
        __syncthreads();
    }
    const float invN = 1.f / (CPG * LL);
    float mean = r0[0] * invN;
    float var = r1[0] * invN - mean * mean;
    float rstd = rsqrtf(var + 1e-5f);

    int h = t & 1;
    float wv[8], bv[8];
#pragma unroll
    for (int j = 0; j < 8; j++) {
        int cg = g * CPG + h * 8 + j;
        wv[j] = gw[cg] * rstd;
        bv[j] = gb[cg] - mean * wv[j];
    }

    for (int u = t; u < 2 * LL; u += 256) {
        int l = u >> 1;
        uint4 pack;
        __half2* ph = (__half2*)&pack;
#pragma unroll
        for (int j = 0; j < 4; j++) {
            float v0 = xp[(size_t)(h * 8 + 2 * j) * LL + l];
            float v1 = xp[(size_t)(h * 8 + 2 * j + 1) * LL + l];
            ph[j] = __floats2half2_rn(v0 * wv[2 * j] + bv[2 * j],
                                      v1 * wv[2 * j + 1] + bv[2 * j + 1]);
        }
        *(uint4*)(g_hT + ((size_t)b * LL + l) * CC + g * CPG + h * 8) = pack;
    }
}

// ---------------------------------------------------------------------------
// Kernel 2: unified QKV GEMM, 128x128 tiles, K-chunk 64, 3-stage ring, one
// sync per iteration. Epilogue staged through smem for coalesced stores.
// ---------------------------------------------------------------------------
#define GP 72
#define GTILE (128 * GP)
#define GSMEM (6 * GTILE * 2)
#define EPST 136

__global__ void __launch_bounds__(256, 2) qkv_gemm(const float* __restrict__ bias) {
    extern __shared__ __half dyn[];
    __half* As[3] = {dyn, dyn + GTILE, dyn + 2 * GTILE};
    __half* Bs[3] = {dyn + 3 * GTILE, dyn + 4 * GTILE, dyn + 5 * GTILE};

    int id = blockIdx.x;
    bool isqk = id < 1024;
    int b, o0, l0;
    const __half *Asrc, *Bsrc;
    if (isqk) {
        int r = id & 63;
        b = id >> 6;
        l0 = (r & 7) * 128; o0 = (r >> 3) * 128;
        Asrc = g_hT + ((size_t)b * LL + l0) * CC;
        Bsrc = g_wh + (size_t)o0 * CC;
    } else {
        int id2 = id - 1024;
        int r = id2 & 31;
        b = id2 >> 5;
        l0 = (r & 7) * 128; o0 = (r >> 3) * 128;
        Asrc = g_wh + (size_t)(2 * CC + o0) * CC;
        Bsrc = g_hT + ((size_t)b * LL + l0) * CC;
    }
    int t = threadIdx.x, warp = t >> 5, lane = t & 31;
    int g = lane >> 2, tt = lane & 3;
    int wm = warp >> 2, wn = warp & 3;

    int sr = t >> 3, sc = (t & 7) * 8;

    int arow = (lane & 7) + 8 * ((lane >> 3) & 1);
    int acol = 8 * (lane >> 4);
    int brow = (lane & 7) + 8 * ((lane >> 4) & 1);
    int bcol = 8 * ((lane >> 3) & 1);
    unsigned aoff = (unsigned)((wm * 64 + arow) * GP + acol) * 2;
    unsigned boff = (unsigned)((wn * 32 + brow) * GP + bcol) * 2;
    unsigned sA[3], sB[3];
#pragma unroll
    for (int i = 0; i < 3; i++) {
        sA[i] = (unsigned)__cvta_generic_to_shared(As[i]) + aoff;
        sB[i] = (unsigned)__cvta_generic_to_shared(Bs[i]) + boff;
    }

    float acc[4][4][4];
#pragma unroll
    for (int m = 0; m < 4; m++)
#pragma unroll
        for (int n = 0; n < 4; n++)
#pragma unroll
            for (int r = 0; r < 4; r++) acc[m][n][r] = 0.f;

#pragma unroll
    for (int i = 0; i < 4; i++) {
        int rw = sr + i * 32;
        cp16h(&As[0][rw * GP + sc], Asrc + (size_t)rw * CC + sc);
        cp16h(&Bs[0][rw * GP + sc], Bsrc + (size_t)rw * CC + sc);
    }
    cp_commit();
#pragma unroll
    for (int i = 0; i < 4; i++) {
        int rw = sr + i * 32;
        cp16h(&As[1][rw * GP + sc], Asrc + (size_t)rw * CC + 64 + sc);
        cp16h(&Bs[1][rw * GP + sc], Bsrc + (size_t)rw * CC + 64 + sc);
    }
    cp_commit();

    int kcur = 0, kst = 2;
    for (int ic = 0; ic < 8; ic++) {
        cp_wait1();
        __syncthreads();

#pragma unroll
        for (int kk = 0; kk < 4; kk++) {
            unsigned a[4][4], bb[2][4];
#pragma unroll
            for (int mm = 0; mm < 4; mm++)
                ldsm4(a[mm], sA[kcur] + (unsigned)(mm * 16 * GP + kk * 16) * 2);
#pragma unroll
            for (int i = 0; i < 2; i++)
                ldsm4(bb[i], sB[kcur] + (unsigned)(i * 16 * GP + kk * 16) * 2);
#pragma unroll
            for (int mm = 0; mm < 4; mm++)
#pragma unroll
                for (int nn = 0; nn < 4; nn++) {
                    unsigned bf[2] = {bb[nn >> 1][2 * (nn & 1)],
                                      bb[nn >> 1][2 * (nn & 1) + 1]};
                    mma_f16(acc[mm][nn], a[mm], bf);
                }
        }

        if (ic + 2 < 8) {
            int c0 = (ic + 2) * 64;
#pragma unroll
            for (int i = 0; i < 4; i++) {
                int rw = sr + i * 32;
                cp16h(&As[kst][rw * GP + sc], Asrc + (size_t)rw * CC + c0 + sc);
                cp16h(&Bs[kst][rw * GP + sc], Bsrc + (size_t)rw * CC + c0 + sc);
            }
        }
        cp_commit();

        kcur = (kcur + 1 == 3) ? 0 : kcur + 1;
        kst = (kst + 1 == 3) ? 0 : kst + 1;
    }

    // ---- epilogue: stage bias/scale-applied tile in smem, coalesced stores ----
    __syncthreads();                 // fence last chunk's ldsm before EP overwrite
    __half* EP = dyn;                // 128 x EPST halfs = 34.8KB (fits As[0..1])
    const float QSC = 0.125f * 1.4426950408889634f;

    if (isqk) {
        int sec = o0 >> 9, h0 = (o0 >> 6) & 7;
        float sc2 = (sec == 0) ? QSC : 1.f;
#pragma unroll
        for (int mm = 0; mm < 4; mm++) {
            int row = wm * 64 + mm * 16 + g;
#pragma unroll
            for (int nn = 0; nn < 4; nn++) {
                int col = wn * 32 + nn * 8 + 2 * tt;
                float2 b2 = *(const float2*)&bias[o0 + col];
                *(__half2*)&EP[row * EPST + col] =
                    __floats2half2_rn((acc[mm][nn][0] + b2.x) * sc2,
                                      (acc[mm][nn][1] + b2.y) * sc2);
                *(__half2*)&EP[(row + 8) * EPST + col] =
                    __floats2half2_rn((acc[mm][nn][2] + b2.x) * sc2,
                                      (acc[mm][nn][3] + b2.y) * sc2);
            }
        }
        __syncthreads();
        __half* base0 = g_qkT + (((size_t)b * 2 + sec) * 8 + h0) * LL * CHH;
        __half* base1 = g_qkT + (((size_t)b * 2 + sec) * 8 + h0 + 1) * LL * CHH;
#pragma unroll
        for (int k = 0; k < 8; k++) {
            int idx = t + k * 256;
            int row = idx >> 4, u4 = idx & 15;
            uint4 v = *(uint4*)&EP[row * EPST + u4 * 8];
            __half* dst = (u4 < 8 ? base0 : base1) + (size_t)(l0 + row) * CHH + (u4 & 7) * 8;
            *(uint4*)dst = v;
        }
    } else {
#pragma unroll
        for (int mm = 0; mm < 4; mm++) {
            int row = wm * 64 + mm * 16 + g;   // o-local
            float b0 = bias[2 * CC + o0 + row], b1 = bias[2 * CC + o0 + row + 8];
#pragma unroll
            for (int nn = 0; nn < 4; nn++) {
                int col = wn * 32 + nn * 8 + 2 * tt;   // l-local
                *(__half2*)&EP[row * EPST + col] =
                    __floats2half2_rn(acc[mm][nn][0] + b0, acc[mm][nn][1] + b0);
                *(__half2*)&EP[(row + 8) * EPST + col] =
                    __floats2half2_rn(acc[mm][nn][2] + b1, acc[mm][nn][3] + b1);
            }
        }
        __syncthreads();
        __half* vb = g_v + (size_t)b * CC * LL;
#pragma unroll
        for (int k = 0; k < 8; k++) {
            int idx = t + k * 256;
            int row = idx >> 4, u4 = idx & 15;
            uint4 v = *(uint4*)&EP[row * EPST + u4 * 8];
            *(uint4*)(vb + (size_t)(o0 + row) * LL + l0 + u4 * 8) = v;
        }
    }
}

// ---------------------------------------------------------------------------
// Kernel 3: flash attention, 256 threads / 128-query tile. Row-sum l computed
// on the tensor core via an all-ones B fragment.
// ---------------------------------------------------------------------------
#define FPAD 72
#define TILE_B (64 * FPAD * 2)
#define FSMEM (8 * TILE_B)          // Q(2) + K0..K2 + V0..V2
#define AS_ST 132

__global__ void __launch_bounds__(256, 2) attn_flash(const float* __restrict__ x,
                                                     float* __restrict__ out) {
    extern __shared__ char smc[];
    __half* Qs = (__half*)smc;                       // tiles 0-1: 128 rows
    __half* Kb[3] = {(__half*)(smc + 2 * TILE_B), (__half*)(smc + 3 * TILE_B),
                     (__half*)(smc + 4 * TILE_B)};
    __half* Vb[3] = {(__half*)(smc + 5 * TILE_B), (__half*)(smc + 6 * TILE_B),
                     (__half*)(smc + 7 * TILE_B)};

    int q0 = blockIdx.x;                 // 0..7 (128 queries each)
    int bh = blockIdx.y;                 // 0..127
    int b = bh >> 3, head = bh & 7;
    int t = threadIdx.x, warp = t >> 5, lane = t & 31;
    int g = lane >> 2, tt = lane & 3;

    const __half* qbase = g_qkT + (((size_t)b * 2 + 0) * 8 + head) * LL * CHH;
    const __half* kbase = g_qkT + (((size_t)b * 2 + 1) * 8 + head) * LL * CHH;
    const __half* vbase = g_v + ((size_t)b * CC + head * CHH) * LL;

    int sr = t >> 3, sc = (t & 7) * 8;   // K/V rows sr, sr+32

    int brow = (lane & 7) + 8 * ((lane >> 4) & 1);
    int bcol = 8 * ((lane >> 3) & 1);
    unsigned kvoff = (unsigned)(brow * FPAD + bcol) * 2;
    unsigned sK[3], sV[3];
#pragma unroll
    for (int i = 0; i < 3; i++) {
        sK[i] = (unsigned)__cvta_generic_to_shared(Kb[i]) + kvoff;
        sV[i] = (unsigned)__cvta_generic_to_shared(Vb[i]) + kvoff;
    }

    // prologue: g0 = {Q(4/thr), K0, V0}; g1 = {K1, V1}
#pragma unroll
    for (int i = 0; i < 4; i++) {
        int rw = sr + i * 32;
        cp16h(&Qs[rw * FPAD + sc], qbase + (size_t)(q0 * 128 + rw) * CHH + sc);
    }
#pragma unroll
    for (int i = 0; i < 2; i++) {
        int rw = sr + i * 32;
        cp16h(&Kb[0][rw * FPAD + sc], kbase + (size_t)rw * CHH + sc);
        cp16h(&Vb[0][rw * FPAD + sc], vbase + (size_t)rw * LL + sc);
    }
    cp_commit();
#pragma unroll
    for (int i = 0; i < 2; i++) {
        int rw = sr + i * 32;
        cp16h(&Kb[1][rw * FPAD + sc], kbase + (size_t)(64 + rw) * CHH + sc);
        cp16h(&Vb[1][rw * FPAD + sc], vbase + (size_t)rw * LL + 64 + sc);
    }
    cp_commit();

    float m0 = -INFINITY, m1 = -INFINITY;
    float lacc[4] = {0.f, 0.f, 0.f, 0.f};   // tensor-core row sums
    float o[8][4];
#pragma unroll
    for (int j = 0; j < 8; j++)
#pragma unroll
        for (int r = 0; r < 4; r++) o[j][r] = 0.f;

    const unsigned ONES2 = 0x3C003C00u;      // {1.0h, 1.0h}

    cp_wait1();
    __syncthreads();
    unsigned qa[4][4];
    {
        const __half* qp = &Qs[(warp * 16 + g) * FPAD];
#pragma unroll
        for (int kk = 0; kk < 4; kk++) {
            const __half* p = qp + kk * 16 + 2 * tt;
            qa[kk][0] = *(const unsigned*)p;
            qa[kk][1] = *(const unsigned*)(p + 8 * FPAD);
            qa[kk][2] = *(const unsigned*)(p + 8);
            qa[kk][3] = *(const unsigned*)(p + 8 * FPAD + 8);
        }
    }

    int kcur = 0, kst = 2;
    for (int ic = 0; ic < 16; ic++) {
        cp_wait1();
        __syncthreads();

        unsigned K = sK[kcur], V = sV[kcur];

        // ---- S = Q K^T (log2 domain via q pre-scale) ----
        float d[8][4];
#pragma unroll
        for (int j = 0; j < 8; j++)
            d[j][0] = d[j][1] = d[j][2] = d[j][3] = 0.f;
#pragma unroll
        for (int kk = 0; kk < 4; kk++)
#pragma unroll
            for (int i = 0; i < 4; i++) {
                unsigned r[4];
                ldsm4(r, K + (unsigned)(i * 16 * FPAD + kk * 16) * 2);
                unsigned blo[2] = {r[0], r[1]}, bhi[2] = {r[2], r[3]};
                mma_f16(d[2 * i], qa[kk], blo);
                mma_f16(d[2 * i + 1], qa[kk], bhi);
            }

        // ---- online softmax (exp2 domain, f16x2 MUFU) ----
        float cm0 = -INFINITY, cm1 = -INFINITY;
#pragma unroll
        for (int j = 0; j < 8; j++) {
            cm0 = fmaxf(cm0, fmaxf(d[j][0], d[j][1]));
            cm1 = fmaxf(cm1, fmaxf(d[j][2], d[j][3]));
        }
        cm0 = fmaxf(cm0, __shfl_xor_sync(0xffffffffu, cm0, 1));
        cm0 = fmaxf(cm0, __shfl_xor_sync(0xffffffffu, cm0, 2));
        cm1 = fmaxf(cm1, __shfl_xor_sync(0xffffffffu, cm1, 1));
        cm1 = fmaxf(cm1, __shfl_xor_sync(0xffffffffu, cm1, 2));

        float mn0 = fmaxf(m0, cm0), mn1 = fmaxf(m1, cm1);
        float al0 = exp2f(m0 - mn0), al1 = exp2f(m1 - mn1);
        m0 = mn0; m1 = mn1;

        unsigned p2[8][2];
#pragma unroll
        for (int j = 0; j < 8; j++) {
            __half2 s01 = __floats2half2_rn(d[j][0] - m0, d[j][1] - m0);
            __half2 s23 = __floats2half2_rn(d[j][2] - m1, d[j][3] - m1);
            p2[j][0] = ex2_f16x2(*(unsigned*)&s01);
            p2[j][1] = ex2_f16x2(*(unsigned*)&s23);
        }

#pragma unroll
        for (int j = 0; j < 8; j++) {
            o[j][0] *= al0; o[j][1] *= al0;
            o[j][2] *= al1; o[j][3] *= al1;
        }
        lacc[0] *= al0; lacc[1] *= al0;
        lacc[2] *= al1; lacc[3] *= al1;

        // ---- O += P V^T ; l += P @ ones ----
#pragma unroll
        for (int kk = 0; kk < 4; kk++) {
            unsigned a[4] = {p2[2 * kk][0], p2[2 * kk][1],
                             p2[2 * kk + 1][0], p2[2 * kk + 1][1]};
#pragma unroll
            for (int i = 0; i < 4; i++) {
                unsigned r[4];
                ldsm4(r, V + (unsigned)(i * 16 * FPAD + kk * 16) * 2);
                unsigned blo[2] = {r[0], r[1]}, bhi[2] = {r[2], r[3]};
                mma_f16(o[2 * i], a, blo);
                mma_f16(o[2 * i + 1], a, bhi);
            }
            unsigned bones[2] = {ONES2, ONES2};
            mma_f16(lacc, a, bones);
        }

        // ---- stage chunk ic+2 into slot kst ----
        if (ic + 2 < 16) {
            __half* Kn = Kb[kst];
            __half* Vn = Vb[kst];
            int s0 = (ic + 2) * 64;
#pragma unroll
            for (int i = 0; i < 2; i++) {
                int rw = sr + i * 32;
                cp16h(&Kn[rw * FPAD + sc], kbase + (size_t)(s0 + rw) * CHH + sc);
                cp16h(&Vn[rw * FPAD + sc], vbase + (size_t)rw * LL + s0 + sc);
            }
        }
        cp_commit();

        kcur = (kcur + 1 == 3) ? 0 : kcur + 1;
        kst = (kst + 1 == 3) ? 0 : kst + 1;
    }

    __syncthreads();   // AS overlaps Q/K tiles; fence iter-15 readers

    // ---- epilogue: A[ch][q] staged in smem, float4 residual-add ----
    float* AS = (float*)smc;   // 64 x 132 fp32 = 33.8KB
    float inv0 = 1.f / lacc[0], inv1 = 1.f / lacc[2];
    int qg = warp * 16 + g;
#pragma unroll
    for (int j = 0; j < 8; j++) {
        int ch = j * 8 + 2 * tt;
        AS[ch * AS_ST + qg] = o[j][0] * inv0;
        AS[(ch + 1) * AS_ST + qg] = o[j][1] * inv0;
        AS[ch * AS_ST + qg + 8] = o[j][2] * inv1;
        AS[(ch + 1) * AS_ST + qg + 8] = o[j][3] * inv1;
    }
    __syncthreads();
#pragma unroll
    for (int k = 0; k < 8; k++) {
        int idx = t + k * 256;                 // over 2048 float4 groups
        int ch = idx >> 5, q4 = (idx & 31) * 4;
        size_t gi = ((size_t)b * CC + head * CHH + ch) * LL + q0 * 128 + q4;
        float4 xa = *(const float4*)&x[gi];
        float4 av = *(const float4*)&AS[ch * AS_ST + q4];
        xa.x += av.x; xa.y += av.y; xa.z += av.z; xa.w += av.w;
        *(float4*)&out[gi] = xa;
    }
}

// ---------------------------------------------------------------------------
extern "C" void kernel_launch(void* const* d_in, const int* in_sizes, int n_in,
                              void* d_out, int out_size) {
    const float* x = (const float*)d_in[0];
    const float* gn_w = (const float*)d_in[1];
    const float* gn_b = (const float*)d_in[2];
    const float* conv_w = (const float*)d_in[3];
    const float* conv_b = (const float*)d_in[4];
    float* out = (float*)d_out;

    wconv_kernel<<<3 * CC * CC / 512, 256>>>(conv_w);
    gn_kernel<<<BB * GG, 256>>>(x, gn_w, gn_b);

    cudaFuncSetAttribute(qkv_gemm, cudaFuncAttributeMaxDynamicSharedMemorySize,
                         GSMEM);
    qkv_gemm<<<1536, 256, GSMEM>>>(conv_b);

    cudaFuncSetAttribute(attn_flash, cudaFuncAttributeMaxDynamicSharedMemorySize,
                         FSMEM);
    dim3 attn_grid(LL / 128, BB * HEADS);
    attn_flash<<<attn_grid, 256, FSMEM>>>(x, out);
}